// round 3
// baseline (speedup 1.0000x reference)
#include <cuda_runtime.h>
#include <cuda_bf16.h>
#include <math.h>

// ---------------------------------------------------------------------------
// Problem constants
//   b=16, s=512, d=2048, H=16 heads, hd=128, G=4 kv groups, P=4 heads/group
// ---------------------------------------------------------------------------
#define BB 16
#define SS 512
#define DD 2048
#define NH 16
#define HD 128
#define NG 4
#define MROWS (BB * SS)          // 8192

// Scratch (device globals: allocation-free rule)
__device__ float g_q[MROWS * DD];          // (b,s,H,hd) = 64MB
__device__ float g_k[MROWS * NG * HD];     // (b,s,G,hd) = 16MB
__device__ float g_v[MROWS * NG * HD];     // 16MB
__device__ float g_ctx[MROWS * DD];        // 64MB

// ---------------------------------------------------------------------------
// SGEMM: C[M,N] = A[M,K] @ B[K,N] + bias[N]   (all row-major fp32)
// 128x128 block tile, BK=16, 8x8 per-thread, 256 threads, double-buffered.
// M,N,K all multiples of tile sizes for this problem -> no bounds checks.
// ---------------------------------------------------------------------------
__global__ __launch_bounds__(256)
void sgemm_kernel(const float* __restrict__ A, const float* __restrict__ B,
                  const float* __restrict__ bias, float* __restrict__ C,
                  int M, int N, int K)
{
    __shared__ float As[2][16][128];
    __shared__ float Bs[2][16][128];

    const int tid = threadIdx.x;
    const int ty  = tid >> 4;         // 0..15
    const int tx  = tid & 15;         // 0..15
    const int m0  = blockIdx.y << 7;
    const int n0  = blockIdx.x << 7;

    // A-tile load mapping: 128 rows x 16 k, each thread 2x float4 along k
    const int ra = tid >> 2;          // 0..63
    const int ka = (tid & 3) << 2;    // 0,4,8,12
    // B-tile load mapping: 16 k rows x 128 cols, each thread 2x float4 along n
    const int rb = tid >> 5;          // 0..7
    const int cb = (tid & 31) << 2;   // 0..124

    const float* Ap = A + (m0 + ra) * K + ka;
    const float* Bp = B + rb * N + (n0 + cb);

    float acc[8][8];
#pragma unroll
    for (int i = 0; i < 8; ++i)
#pragma unroll
        for (int j = 0; j < 8; ++j) acc[i][j] = 0.f;

    // prologue: tile 0
    {
        float4 a0 = *(const float4*)(Ap);
        float4 a1 = *(const float4*)(Ap + 64 * K);
        float4 b0 = *(const float4*)(Bp);
        float4 b1 = *(const float4*)(Bp + 8 * N);
        As[0][ka+0][ra] = a0.x; As[0][ka+1][ra] = a0.y;
        As[0][ka+2][ra] = a0.z; As[0][ka+3][ra] = a0.w;
        As[0][ka+0][ra+64] = a1.x; As[0][ka+1][ra+64] = a1.y;
        As[0][ka+2][ra+64] = a1.z; As[0][ka+3][ra+64] = a1.w;
        *(float4*)&Bs[0][rb][cb]   = b0;
        *(float4*)&Bs[0][rb+8][cb] = b1;
    }
    __syncthreads();

    const int ntiles = K >> 4;
    int buf = 0;
    for (int t = 0; t < ntiles; ++t) {
        float4 a0, a1, b0, b1;
        const bool pf = (t + 1 < ntiles);
        if (pf) {
            const float* Ap2 = Ap + ((t + 1) << 4);
            const float* Bp2 = Bp + ((t + 1) << 4) * N;
            a0 = *(const float4*)(Ap2);
            a1 = *(const float4*)(Ap2 + 64 * K);
            b0 = *(const float4*)(Bp2);
            b1 = *(const float4*)(Bp2 + 8 * N);
        }
#pragma unroll
        for (int k = 0; k < 16; ++k) {
            float ar[8], br[8];
            *(float4*)&ar[0] = *(float4*)&As[buf][k][ty * 8];
            *(float4*)&ar[4] = *(float4*)&As[buf][k][ty * 8 + 4];
            *(float4*)&br[0] = *(float4*)&Bs[buf][k][tx * 8];
            *(float4*)&br[4] = *(float4*)&Bs[buf][k][tx * 8 + 4];
#pragma unroll
            for (int i = 0; i < 8; ++i)
#pragma unroll
                for (int j = 0; j < 8; ++j)
                    acc[i][j] = fmaf(ar[i], br[j], acc[i][j]);
        }
        if (pf) {
            const int nb = buf ^ 1;
            As[nb][ka+0][ra] = a0.x; As[nb][ka+1][ra] = a0.y;
            As[nb][ka+2][ra] = a0.z; As[nb][ka+3][ra] = a0.w;
            As[nb][ka+0][ra+64] = a1.x; As[nb][ka+1][ra+64] = a1.y;
            As[nb][ka+2][ra+64] = a1.z; As[nb][ka+3][ra+64] = a1.w;
            *(float4*)&Bs[nb][rb][cb]   = b0;
            *(float4*)&Bs[nb][rb+8][cb] = b1;
            __syncthreads();
            buf = nb;
        }
    }

    // epilogue: add bias, write
    float bb0[8];
#pragma unroll
    for (int j = 0; j < 8; ++j) bb0[j] = bias[n0 + tx * 8 + j];
#pragma unroll
    for (int i = 0; i < 8; ++i) {
        const int row = m0 + ty * 8 + i;
        float* Cp = C + row * N + n0 + tx * 8;
        float4 o0, o1;
        o0.x = acc[i][0] + bb0[0]; o0.y = acc[i][1] + bb0[1];
        o0.z = acc[i][2] + bb0[2]; o0.w = acc[i][3] + bb0[3];
        o1.x = acc[i][4] + bb0[4]; o1.y = acc[i][5] + bb0[5];
        o1.z = acc[i][6] + bb0[6]; o1.w = acc[i][7] + bb0[7];
        *(float4*)Cp       = o0;
        *(float4*)(Cp + 4) = o1;
    }
}

// ---------------------------------------------------------------------------
// RMSNorm + RoPE, fused. X viewed as [B*S*nh][128] rows.
// One warp per row (4 floats/lane). RoPE pair i uses elems (2i, 2i+1):
//   out[2i]   = y[2i]*cos(t*f_i) - y[2i+1]*sin(t*f_i)
//   out[2i+1] = y[2i]*sin(t*f_i) + y[2i+1]*cos(t*f_i)
// with f_i = 10000^{-2i/128}. extra = post-rope scalar (1/128 for q).
// ---------------------------------------------------------------------------
__global__ __launch_bounds__(256)
void norm_rope_kernel(float* __restrict__ X, const float* __restrict__ scale,
                      int nh, float extra)
{
    const int warp = threadIdx.x >> 5;
    const int lane = threadIdx.x & 31;
    const int row  = blockIdx.x * 8 + warp;
    const int t    = (row / nh) & (SS - 1);

    float* p = X + (size_t)row * HD + lane * 4;
    float4 v = *(float4*)p;

    float ss = v.x * v.x + v.y * v.y + v.z * v.z + v.w * v.w;
#pragma unroll
    for (int o = 16; o; o >>= 1) ss += __shfl_xor_sync(0xffffffffu, ss, o);
    const float r = rsqrtf(ss * (1.0f / 128.0f) + 1e-6f);

    float4 sc = *(const float4*)(scale + lane * 4);
    float y0 = v.x * r * sc.x;
    float y1 = v.y * r * sc.y;
    float y2 = v.z * r * sc.z;
    float y3 = v.w * r * sc.w;

    const int i0 = lane * 2;
    const float LN1E4 = 9.2103403719761836f;  // ln(10000)
    float f0 = expf(-((float)(2 * i0)     * (1.0f / 128.0f)) * LN1E4);
    float f1 = expf(-((float)(2 * i0 + 2) * (1.0f / 128.0f)) * LN1E4);
    float s0, c0, s1, c1;
    sincosf((float)t * f0, &s0, &c0);
    sincosf((float)t * f1, &s1, &c1);

    float4 o;
    o.x = (y0 * c0 - y1 * s0) * extra;
    o.y = (y0 * s0 + y1 * c0) * extra;
    o.z = (y2 * c1 - y3 * s1) * extra;
    o.w = (y2 * s1 + y3 * c1) * extra;
    *(float4*)p = o;
}

// ---------------------------------------------------------------------------
// Causal flash attention, fp32.
// Grid: (q_tiles=8, heads=16, batch=16). Block: 256 threads.
// 64-row q tile resident in smem; loop 64-wide KV tiles; online softmax.
// Per-thread: 4 q rows (ty) x 4 kv cols (tx) for S; 4 rows x 8 interleaved
// out cols (tx + 16*c) for O. Row reductions via 16-lane shfl butterflies.
// Scale (1/128) is pre-folded into q by norm_rope_kernel.
// ---------------------------------------------------------------------------
#define QS_LD 129
#define PS_LD 68
#define ATTN_SMEM ((2 * 64 * QS_LD + 64 * PS_LD) * 4)   // 83456 bytes

__global__ __launch_bounds__(256)
void attn_kernel(const float* __restrict__ Q, const float* __restrict__ Kg,
                 const float* __restrict__ Vg, float* __restrict__ ctx)
{
    extern __shared__ float sm[];
    float* Qs = sm;                       // [64][129]
    float* Ks = sm + 64 * QS_LD;          // [64][129], reused for V
    float* Ps = sm + 2 * 64 * QS_LD;      // [64][68]

    const int tid = threadIdx.x;
    const int tx  = tid & 15;
    const int ty  = tid >> 4;
    const int q0  = blockIdx.x << 6;
    const int h   = blockIdx.y;
    const int b   = blockIdx.z;
    const int g   = h >> 2;

    // load Q tile (64 x 128)
    for (int f = tid; f < 2048; f += 256) {
        const int r = f >> 5, c = (f & 31) << 2;
        float4 v = *(const float4*)(Q + ((size_t)((b * SS + q0 + r) * NH + h)) * HD + c);
        float* d = Qs + r * QS_LD + c;
        d[0] = v.x; d[1] = v.y; d[2] = v.z; d[3] = v.w;
    }

    float m_run[4], l_run[4], Ob[4][8];
#pragma unroll
    for (int i = 0; i < 4; ++i) {
        m_run[i] = -1e30f; l_run[i] = 0.f;
#pragma unroll
        for (int c = 0; c < 8; ++c) Ob[i][c] = 0.f;
    }

    const float* q_r0 = Qs + (ty * 4 + 0) * QS_LD;
    const float* q_r1 = Qs + (ty * 4 + 1) * QS_LD;
    const float* q_r2 = Qs + (ty * 4 + 2) * QS_LD;
    const float* q_r3 = Qs + (ty * 4 + 3) * QS_LD;
    const float* k_r0 = Ks + (tx * 4 + 0) * QS_LD;
    const float* k_r1 = Ks + (tx * 4 + 1) * QS_LD;
    const float* k_r2 = Ks + (tx * 4 + 2) * QS_LD;
    const float* k_r3 = Ks + (tx * 4 + 3) * QS_LD;

    for (int j0 = 0; j0 <= q0; j0 += 64) {
        __syncthreads();   // previous PV reads of Ks done
        // load K tile
        for (int f = tid; f < 2048; f += 256) {
            const int r = f >> 5, c = (f & 31) << 2;
            float4 v = *(const float4*)(Kg + ((size_t)((b * SS + j0 + r) * NG + g)) * HD + c);
            float* d = Ks + r * QS_LD + c;
            d[0] = v.x; d[1] = v.y; d[2] = v.z; d[3] = v.w;
        }
        __syncthreads();

        // S = Q @ K^T  (4x4 per thread)
        float acc[4][4];
#pragma unroll
        for (int i = 0; i < 4; ++i)
#pragma unroll
            for (int j = 0; j < 4; ++j) acc[i][j] = 0.f;

#pragma unroll 4
        for (int d = 0; d < HD; ++d) {
            const float a0 = q_r0[d], a1 = q_r1[d], a2 = q_r2[d], a3 = q_r3[d];
            const float b0 = k_r0[d], b1 = k_r1[d], b2 = k_r2[d], b3 = k_r3[d];
            acc[0][0] = fmaf(a0, b0, acc[0][0]); acc[0][1] = fmaf(a0, b1, acc[0][1]);
            acc[0][2] = fmaf(a0, b2, acc[0][2]); acc[0][3] = fmaf(a0, b3, acc[0][3]);
            acc[1][0] = fmaf(a1, b0, acc[1][0]); acc[1][1] = fmaf(a1, b1, acc[1][1]);
            acc[1][2] = fmaf(a1, b2, acc[1][2]); acc[1][3] = fmaf(a1, b3, acc[1][3]);
            acc[2][0] = fmaf(a2, b0, acc[2][0]); acc[2][1] = fmaf(a2, b1, acc[2][1]);
            acc[2][2] = fmaf(a2, b2, acc[2][2]); acc[2][3] = fmaf(a2, b3, acc[2][3]);
            acc[3][0] = fmaf(a3, b0, acc[3][0]); acc[3][1] = fmaf(a3, b1, acc[3][1]);
            acc[3][2] = fmaf(a3, b2, acc[3][2]); acc[3][3] = fmaf(a3, b3, acc[3][3]);
        }

        // causal mask (only the diagonal tile is partial)
        if (j0 == q0) {
#pragma unroll
            for (int i = 0; i < 4; ++i)
#pragma unroll
                for (int j = 0; j < 4; ++j)
                    if (tx * 4 + j > ty * 4 + i) acc[i][j] = -1e30f;
        }

        // online softmax per row (state replicated across the 16 tx lanes)
#pragma unroll
        for (int i = 0; i < 4; ++i) {
            float mx = fmaxf(fmaxf(acc[i][0], acc[i][1]), fmaxf(acc[i][2], acc[i][3]));
#pragma unroll
            for (int o = 8; o; o >>= 1)
                mx = fmaxf(mx, __shfl_xor_sync(0xffffffffu, mx, o, 16));
            const float mnew = fmaxf(m_run[i], mx);
            const float corr = __expf(m_run[i] - mnew);
            float rs = 0.f;
#pragma unroll
            for (int j = 0; j < 4; ++j) {
                const float p = __expf(acc[i][j] - mnew);
                acc[i][j] = p; rs += p;
            }
#pragma unroll
            for (int o = 8; o; o >>= 1)
                rs += __shfl_xor_sync(0xffffffffu, rs, o, 16);
            l_run[i] = l_run[i] * corr + rs;
            m_run[i] = mnew;
#pragma unroll
            for (int c = 0; c < 8; ++c) Ob[i][c] *= corr;
            float* pp = Ps + (ty * 4 + i) * PS_LD + tx * 4;
            pp[0] = acc[i][0]; pp[1] = acc[i][1];
            pp[2] = acc[i][2]; pp[3] = acc[i][3];
        }
        __syncthreads();   // Ps visible; S-phase reads of Ks done

        // load V tile into Ks region
        for (int f = tid; f < 2048; f += 256) {
            const int r = f >> 5, c = (f & 31) << 2;
            float4 v = *(const float4*)(Vg + ((size_t)((b * SS + j0 + r) * NG + g)) * HD + c);
            float* d = Ks + r * QS_LD + c;
            d[0] = v.x; d[1] = v.y; d[2] = v.z; d[3] = v.w;
        }
        __syncthreads();

        // O += P @ V    (out cols: tx + 16*c  -> conflict-free V reads)
        const float* p_r0 = Ps + (ty * 4 + 0) * PS_LD;
        const float* p_r1 = Ps + (ty * 4 + 1) * PS_LD;
        const float* p_r2 = Ps + (ty * 4 + 2) * PS_LD;
        const float* p_r3 = Ps + (ty * 4 + 3) * PS_LD;
#pragma unroll 2
        for (int j = 0; j < 64; ++j) {
            const float a0 = p_r0[j], a1 = p_r1[j], a2 = p_r2[j], a3 = p_r3[j];
            const float* vrow = Ks + j * QS_LD + tx;
#pragma unroll
            for (int c = 0; c < 8; ++c) {
                const float vv = vrow[c << 4];
                Ob[0][c] = fmaf(a0, vv, Ob[0][c]);
                Ob[1][c] = fmaf(a1, vv, Ob[1][c]);
                Ob[2][c] = fmaf(a2, vv, Ob[2][c]);
                Ob[3][c] = fmaf(a3, vv, Ob[3][c]);
            }
        }
    }

    // normalize + write ctx  (b, s, h, hd)
#pragma unroll
    for (int i = 0; i < 4; ++i) {
        const float inv = 1.0f / l_run[i];
        float* base = ctx + ((size_t)((b * SS + q0 + ty * 4 + i) * NH + h)) * HD + tx;
#pragma unroll
        for (int c = 0; c < 8; ++c) base[c << 4] = Ob[i][c] * inv;
    }
}

// ---------------------------------------------------------------------------
// kernel_launch
// ---------------------------------------------------------------------------
extern "C" void kernel_launch(void* const* d_in, const int* in_sizes, int n_in,
                              void* d_out, int out_size)
{
    (void)in_sizes; (void)n_in; (void)out_size;
    const float* x  = (const float*)d_in[0];
    const float* Wq = (const float*)d_in[1];
    const float* bq = (const float*)d_in[2];
    const float* Wk = (const float*)d_in[3];
    const float* bk = (const float*)d_in[4];
    const float* Wv = (const float*)d_in[5];
    const float* bv = (const float*)d_in[6];
    const float* Wo = (const float*)d_in[7];
    const float* bo = (const float*)d_in[8];
    const float* q_scale = (const float*)d_in[9];
    const float* k_scale = (const float*)d_in[10];
    float* out = (float*)d_out;

    float *gq, *gk, *gv, *gc;
    cudaGetSymbolAddress((void**)&gq, g_q);
    cudaGetSymbolAddress((void**)&gk, g_k);
    cudaGetSymbolAddress((void**)&gv, g_v);
    cudaGetSymbolAddress((void**)&gc, g_ctx);

    cudaFuncSetAttribute(attn_kernel,
                         cudaFuncAttributeMaxDynamicSharedMemorySize, ATTN_SMEM);

    const dim3 blk(256);

    // Projections
    sgemm_kernel<<<dim3(DD / 128, MROWS / 128), blk>>>(x, Wq, bq, gq, MROWS, DD, DD);
    sgemm_kernel<<<dim3((NG * HD) / 128, MROWS / 128), blk>>>(x, Wk, bk, gk, MROWS, NG * HD, DD);
    sgemm_kernel<<<dim3((NG * HD) / 128, MROWS / 128), blk>>>(x, Wv, bv, gv, MROWS, NG * HD, DD);

    // RMSNorm + RoPE (q gets the combined 1/hd logit scale folded in)
    norm_rope_kernel<<<(MROWS * NH) / 8, blk>>>(gq, q_scale, NH, 1.0f / 128.0f);
    norm_rope_kernel<<<(MROWS * NG) / 8, blk>>>(gk, k_scale, NG, 1.0f);

    // Causal GQA attention
    attn_kernel<<<dim3(SS / 64, NH, BB), blk, ATTN_SMEM>>>(gq, gk, gv, gc);

    // Output projection
    sgemm_kernel<<<dim3(DD / 128, MROWS / 128), blk>>>(gc, Wo, bo, out, MROWS, DD, DD);
}